// round 7
// baseline (speedup 1.0000x reference)
#include <cuda_runtime.h>
#include <cstdint>
#include <cstddef>

#define BATCH 8
#define NPTS  4096
#define CCH   128
#define HOUT  256
#define KNNK  16
#define ROWS  (BATCH * NPTS)

// ---------------- scratch (static __device__ — no runtime allocation) ----------------
__device__ float g_asrc[ROWS * CCH];
__device__ float g_adst[ROWS * CCH];
__device__ float g_val [ROWS * CCH];
__device__ float g_attn[ROWS * CCH];
__device__ int   g_knn [ROWS * KNNK];

// ---------------- packed f32x2 helpers ----------------
__device__ __forceinline__ unsigned long long dup2(float x) {
    unsigned long long r;
    asm("mov.b64 %0, {%1, %1};" : "=l"(r) : "f"(x));
    return r;
}
__device__ __forceinline__ void fma2(unsigned long long& d, unsigned long long a,
                                     unsigned long long b) {
    asm("fma.rn.f32x2 %0, %1, %2, %0;" : "+l"(d) : "l"(a), "l"(b));
}
__device__ __forceinline__ float2 unpack2(unsigned long long v) {
    float2 r;
    asm("mov.b64 {%0, %1}, %2;" : "=f"(r.x), "=f"(r.y) : "l"(v));
    return r;
}

// ---------------- KNN: warp per 4 rows, warp-collective top-16 ------------------------
// (unchanged from R6 — isolates this round's GEMM change)
__global__ __launch_bounds__(256) void knn_kernel(const float* __restrict__ pos) {
    __shared__ float2 sxy[NPTS];   // 32 KB
    __shared__ float  szv[NPTS];   // 16 KB

    const int bpb = NPTS / 32;            // 32 rows per block
    int b  = blockIdx.x / bpb;
    int rb = blockIdx.x % bpb;
    const float* pb = pos + (size_t)b * NPTS * 3;

    for (int t = threadIdx.x; t < NPTS; t += 256) {
        const float* p = pb + t * 3;
        sxy[t] = make_float2(p[0], p[1]);
        szv[t] = p[2];
    }
    __syncthreads();

    int warp = threadIdx.x >> 5;
    int lane = threadIdx.x & 31;
    const unsigned FULL = 0xffffffffu;
    int i0 = rb * 32 + warp * 4;          // this warp's 4 rows

    float3 pi[4];
    unsigned long long cur[4], tk[4];
    float th[4];
#pragma unroll
    for (int r = 0; r < 4; r++) {
        float2 q = sxy[i0 + r];
        pi[r] = make_float3(q.x, q.y, szv[i0 + r]);
        cur[r] = ~0ull;
        tk[r]  = ~0ull;
        th[r]  = __int_as_float(0x7f800000);   // +inf
    }

    for (int j0 = 0; j0 < NPTS; j0 += 32) {
        int j = j0 + lane;
        float2 pj = sxy[j];
        float  zj = szv[j];
#pragma unroll
        for (int r = 0; r < 4; r++) {
            float dx = pi[r].x - pj.x;
            float dy = pi[r].y - pj.y;
            float dz = pi[r].z - zj;
            float d2 = fmaf(dx, dx, fmaf(dy, dy, dz * dz));

            unsigned mask = __ballot_sync(FULL, d2 <= th[r]);   // conservative filter
            if (mask) {                                          // warp-uniform
                unsigned long long key =
                    ((unsigned long long)__float_as_uint(d2) << 32) | (unsigned)j;
                while (mask) {                                   // warp-uniform
                    int src = __ffs(mask) - 1;
                    mask &= mask - 1;
                    unsigned long long cand = __shfl_sync(FULL, key, src);
                    if (cand < tk[r]) {                          // warp-uniform (exact)
                        unsigned long long prev = __shfl_up_sync(FULL, cur[r], 1);
                        bool bigger = cur[r] > cand;
                        unsigned long long ins =
                            (lane > 0 && prev > cand) ? prev : cand;
                        cur[r] = bigger ? ins : cur[r];
                        tk[r] = __shfl_sync(FULL, cur[r], 15);
                        th[r] = __uint_as_float((unsigned)(tk[r] >> 32));
                    }
                }
            }
        }
    }

    if (lane < KNNK) {
#pragma unroll
        for (int r = 0; r < 4; r++)
            g_knn[((size_t)b * NPTS + i0 + r) * KNNK + lane] =
                (int)(unsigned)(cur[r] & 0xffffffffu);
    }
}

// ---------------- GEMM core: C[M x N] = A[M x 128] @ B[128 x N] (+bias) --------------
// 128-thread blocks (no reg cap -> no spills), tile 128M x 64N, 8M x 8N per thread.
// B is stored PRE-DUPLICATED as f32x2 in smem: dup movs leave the inner loop.
// Inner loop per kk: 4 LDS.64 (A) + 4 LDS.128 (Bdup) + 32 FFMA2.
#define GBM 128
#define GBNT 64     // N tile
#define GBK 32
#define SAS 130     // padded (even) stride for transposed A tile

template <int N>
__device__ __forceinline__ void gemm_body(const float* __restrict__ A,
                                          const float* __restrict__ B,
                                          const float* __restrict__ bias,
                                          float* __restrict__ C,
                                          int m0, int n0) {
    __shared__ float sA[GBK * SAS];                    // [k][m] transposed, ~16.6 KB
    __shared__ unsigned long long sBd[GBK * GBNT];     // [k][n] dup'd f32x2, 16 KB

    int tid = threadIdx.x;      // 128 threads
    int tx  = tid & 7;          // n: 8 threads * 8 cols
    int ty  = tid >> 3;         // m: 16 threads * 8 rows

    unsigned long long acc[4][8];
#pragma unroll
    for (int i = 0; i < 4; i++)
#pragma unroll
        for (int j = 0; j < 8; j++) acc[i][j] = 0ull;   // bits of (0.f, 0.f)

    for (int k0 = 0; k0 < CCH; k0 += GBK) {
        // A tile: 128 rows x 32 cols, stored transposed
#pragma unroll
        for (int p = 0; p < 8; p++) {
            int f  = tid + 128 * p;            // 0..1023
            int m  = f >> 3;
            int kq = f & 7;
            float4 a4 = *reinterpret_cast<const float4*>(
                A + (size_t)(m0 + m) * CCH + k0 + kq * 4);
            float* d = sA + (kq * 4) * SAS + m;
            d[0 * SAS] = a4.x;
            d[1 * SAS] = a4.y;
            d[2 * SAS] = a4.z;
            d[3 * SAS] = a4.w;
        }
        // B tile: 32 rows x 64 cols, duplicated to f32x2
#pragma unroll
        for (int p = 0; p < 4; p++) {
            int f  = tid + 128 * p;            // 0..511
            int kr = f >> 4;
            int nq = f & 15;
            float4 b4 = *reinterpret_cast<const float4*>(
                B + (size_t)(k0 + kr) * N + n0 + nq * 4);
            unsigned long long* d = sBd + kr * GBNT + nq * 4;
            d[0] = dup2(b4.x);
            d[1] = dup2(b4.y);
            d[2] = dup2(b4.z);
            d[3] = dup2(b4.w);
        }
        __syncthreads();

#pragma unroll
        for (int kk = 0; kk < GBK; kk++) {
            const float* ap = sA + kk * SAS + ty * 8;   // even offsets -> 8B aligned
            unsigned long long a0 = *reinterpret_cast<const unsigned long long*>(ap + 0);
            unsigned long long a1 = *reinterpret_cast<const unsigned long long*>(ap + 2);
            unsigned long long a2 = *reinterpret_cast<const unsigned long long*>(ap + 4);
            unsigned long long a3 = *reinterpret_cast<const unsigned long long*>(ap + 6);
            const unsigned long long* bp = sBd + kk * GBNT + tx * 8;
            ulonglong2 b01 = *reinterpret_cast<const ulonglong2*>(bp + 0);
            ulonglong2 b23 = *reinterpret_cast<const ulonglong2*>(bp + 2);
            ulonglong2 b45 = *reinterpret_cast<const ulonglong2*>(bp + 4);
            ulonglong2 b67 = *reinterpret_cast<const ulonglong2*>(bp + 6);
            unsigned long long bd[8] = {b01.x, b01.y, b23.x, b23.y,
                                        b45.x, b45.y, b67.x, b67.y};
#pragma unroll
            for (int j = 0; j < 8; j++) {
                fma2(acc[0][j], a0, bd[j]);
                fma2(acc[1][j], a1, bd[j]);
                fma2(acc[2][j], a2, bd[j]);
                fma2(acc[3][j], a3, bd[j]);
            }
        }
        __syncthreads();
    }

    float4 bva = make_float4(0.f, 0.f, 0.f, 0.f);
    float4 bvb = make_float4(0.f, 0.f, 0.f, 0.f);
    if (bias) {
        bva = *reinterpret_cast<const float4*>(bias + n0 + tx * 8);
        bvb = *reinterpret_cast<const float4*>(bias + n0 + tx * 8 + 4);
    }

#pragma unroll
    for (int i = 0; i < 4; i++) {
        float2 c[8];
#pragma unroll
        for (int j = 0; j < 8; j++) c[j] = unpack2(acc[i][j]);
        int m = m0 + ty * 8 + 2 * i;
        float* crow0 = C + (size_t)m * N + n0 + tx * 8;
        float* crow1 = crow0 + N;
        *reinterpret_cast<float4*>(crow0) =
            make_float4(c[0].x + bva.x, c[1].x + bva.y, c[2].x + bva.z, c[3].x + bva.w);
        *reinterpret_cast<float4*>(crow0 + 4) =
            make_float4(c[4].x + bvb.x, c[5].x + bvb.y, c[6].x + bvb.z, c[7].x + bvb.w);
        *reinterpret_cast<float4*>(crow1) =
            make_float4(c[0].y + bva.x, c[1].y + bva.y, c[2].y + bva.z, c[3].y + bva.w);
        *reinterpret_cast<float4*>(crow1 + 4) =
            make_float4(c[4].y + bvb.x, c[5].y + bvb.y, c[6].y + bvb.z, c[7].y + bvb.w);
    }
}

// input projections: z in {0,1,2} -> (Wsrc->g_asrc, Wdst->g_adst, Wval->g_val)
__global__ __launch_bounds__(128) void gemm_in_kernel(const float* __restrict__ x,
                                                      const float* __restrict__ Wsrc,
                                                      const float* __restrict__ Wdst,
                                                      const float* __restrict__ Wval) {
    const float* B;
    float* C;
    switch (blockIdx.z) {
        case 0:  B = Wsrc; C = g_asrc; break;
        case 1:  B = Wdst; C = g_adst; break;
        default: B = Wval; C = g_val;  break;
    }
    gemm_body<CCH>(x, B, nullptr, C, blockIdx.x * GBM, blockIdx.y * GBNT);
}

// output projection: g_attn @ Wout + bout -> out
__global__ __launch_bounds__(128) void gemm_out_kernel(const float* __restrict__ Wout,
                                                       const float* __restrict__ bout,
                                                       float* __restrict__ out) {
    gemm_body<HOUT>(g_attn, Wout, bout, out, blockIdx.x * GBM, blockIdx.y * GBNT);
}

// ---------------- attention: one row per 128-thread block, thread = channel ----------
__global__ __launch_bounds__(128) void attn_kernel(const float* __restrict__ pos,
                                                   const float* __restrict__ Wpos,
                                                   const float* __restrict__ bpos) {
    int row = blockIdx.x;          // b*NPTS + i
    int b   = row >> 12;
    int i   = row & (NPTS - 1);
    int c   = threadIdx.x;

    __shared__ float srel[KNNK][3];
    __shared__ int   sj[KNNK];

    if (c < KNNK) {
        int j = g_knn[(size_t)row * KNNK + c];
        sj[c] = j;
        const float* pb = pos + (size_t)b * NPTS * 3;
        srel[c][0] = pb[i * 3 + 0] - pb[j * 3 + 0];
        srel[c][1] = pb[i * 3 + 1] - pb[j * 3 + 1];
        srel[c][2] = pb[i * 3 + 2] - pb[j * 3 + 2];
    }
    __syncthreads();

    float w0 = Wpos[c];
    float w1 = Wpos[CCH + c];
    float w2 = Wpos[2 * CCH + c];
    float bp = bpos[c];
    float ad = g_adst[(size_t)row * CCH + c];

    float alpha[KNNK], vd[KNNK];
    float mx = -3.4e38f;
#pragma unroll
    for (int k = 0; k < KNNK; k++) {
        int j = sj[k];
        size_t base = ((size_t)b * NPTS + j) * CCH + c;
        float as = g_asrc[base];
        float vv = g_val[base];
        float dl = fmaf(srel[k][0], w0, fmaf(srel[k][1], w1, fmaf(srel[k][2], w2, bp)));
        alpha[k] = (ad - as) + dl;
        vd[k]    = vv + dl;
        mx = fmaxf(mx, alpha[k]);
    }
    float s = 0.f, accv = 0.f;
#pragma unroll
    for (int k = 0; k < KNNK; k++) {
        float e = __expf(alpha[k] - mx);
        s += e;
        accv = fmaf(e, vd[k], accv);
    }
    g_attn[(size_t)row * CCH + c] = accv / s;
}

// ---------------- launch (kernel launches ONLY — graph-capture safe) ----------------
extern "C" void kernel_launch(void* const* d_in, const int* in_sizes, int n_in,
                              void* d_out, int out_size) {
    const float* x    = (const float*)d_in[0];
    const float* pos  = (const float*)d_in[1];
    const float* Wsrc = (const float*)d_in[2];
    const float* Wdst = (const float*)d_in[3];
    const float* Wval = (const float*)d_in[4];
    const float* Wpos = (const float*)d_in[5];
    const float* bpos = (const float*)d_in[6];
    const float* Wout = (const float*)d_in[7];
    const float* bout = (const float*)d_in[8];
    float* out = (float*)d_out;

    knn_kernel<<<BATCH * (NPTS / 32), 256>>>(pos);

    dim3 g1(ROWS / GBM, CCH / GBNT, 3);
    gemm_in_kernel<<<g1, 128>>>(x, Wsrc, Wdst, Wval);

    attn_kernel<<<ROWS, 128>>>(pos, Wpos, bpos);

    dim3 g2(ROWS / GBM, HOUT / GBNT);
    gemm_out_kernel<<<g2, 128>>>(Wout, bout, out);
}

// round 9
// speedup vs baseline: 1.3276x; 1.3276x over previous
#include <cuda_runtime.h>
#include <cstdint>
#include <cstddef>

#define BATCH 8
#define NPTS  4096
#define CCH   128
#define HOUT  256
#define KNNK  16
#define ROWS  (BATCH * NPTS)

// ---------------- scratch (static __device__ — no runtime allocation) ----------------
__device__ float g_asrc[ROWS * CCH];
__device__ float g_adst[ROWS * CCH];
__device__ float g_val [ROWS * CCH];
__device__ float g_attn[ROWS * CCH];
__device__ int   g_knn [ROWS * KNNK];

// ---------------- packed f32x2 helpers ----------------
__device__ __forceinline__ unsigned long long dup2(float x) {
    unsigned long long r;
    asm("mov.b64 %0, {%1, %1};" : "=l"(r) : "f"(x));
    return r;
}
__device__ __forceinline__ unsigned long long pack2(float lo, float hi) {
    unsigned long long r;
    asm("mov.b64 %0, {%1, %2};" : "=l"(r) : "f"(lo), "f"(hi));
    return r;
}
__device__ __forceinline__ void fma2(unsigned long long& d, unsigned long long a,
                                     unsigned long long b) {
    asm("fma.rn.f32x2 %0, %1, %2, %0;" : "+l"(d) : "l"(a), "l"(b));
}
__device__ __forceinline__ unsigned long long add2(unsigned long long a,
                                                   unsigned long long b) {
    unsigned long long r;
    asm("add.rn.f32x2 %0, %1, %2;" : "=l"(r) : "l"(a), "l"(b));
    return r;
}
__device__ __forceinline__ unsigned long long mul2(unsigned long long a,
                                                   unsigned long long b) {
    unsigned long long r;
    asm("mul.rn.f32x2 %0, %1, %2;" : "=l"(r) : "l"(a), "l"(b));
    return r;
}
__device__ __forceinline__ float2 unpack2(unsigned long long v) {
    float2 r;
    asm("mov.b64 {%0, %1}, %2;" : "=f"(r.x), "=f"(r.y) : "l"(v));
    return r;
}

// ---------------- KNN: warp per 8 rows, rows packed pairwise in f32x2 -----------------
// Sorted top-16 keys (ascending) per row live in lanes 0..15, one u64 per lane:
//   key = (float_bits(d2) << 32) | j   (d2 >= 0: bit order == value order; ties by idx)
// Distances for 2 rows are computed per packed f32x2 op (per-half IEEE fp32; op order
// matches the scalar version exactly -> bit-identical d2 -> identical neighbor sets).
// Hot loop: packed dist + per-row float compare + ballot. Slow path (~105 inserts/row):
// warp-uniform shfl_up insertion shift.
__global__ __launch_bounds__(256) void knn_kernel(const float* __restrict__ pos) {
    __shared__ float2 sxy[NPTS];   // 32 KB
    __shared__ float  szv[NPTS];   // 16 KB

    const int bpb = NPTS / 64;            // 64 rows per block (8 warps x 8 rows)
    int b  = blockIdx.x / bpb;
    int rb = blockIdx.x % bpb;
    const float* pb = pos + (size_t)b * NPTS * 3;

    for (int t = threadIdx.x; t < NPTS; t += 256) {
        const float* p = pb + t * 3;
        sxy[t] = make_float2(p[0], p[1]);
        szv[t] = p[2];
    }
    __syncthreads();

    int warp = threadIdx.x >> 5;
    int lane = threadIdx.x & 31;
    const unsigned FULL = 0xffffffffu;
    int i0 = rb * 64 + warp * 8;          // this warp's 8 rows

    unsigned long long px[4], py[4], pz[4];     // packed (row 2p, row 2p+1)
    unsigned long long cur[8], tk[8];
    float th[8];
#pragma unroll
    for (int p = 0; p < 4; p++) {
        float2 qa = sxy[i0 + 2 * p];
        float2 qb = sxy[i0 + 2 * p + 1];
        px[p] = pack2(qa.x, qb.x);
        py[p] = pack2(qa.y, qb.y);
        pz[p] = pack2(szv[i0 + 2 * p], szv[i0 + 2 * p + 1]);
    }
#pragma unroll
    for (int r = 0; r < 8; r++) {
        cur[r] = ~0ull;
        tk[r]  = ~0ull;
        th[r]  = __int_as_float(0x7f800000);   // +inf
    }

    for (int j0 = 0; j0 < NPTS; j0 += 32) {
        int j = j0 + lane;
        float2 pj = sxy[j];
        float  zj = szv[j];
        unsigned long long njx = dup2(-pj.x);
        unsigned long long njy = dup2(-pj.y);
        unsigned long long njz = dup2(-zj);
#pragma unroll
        for (int p = 0; p < 4; p++) {
            unsigned long long dx = add2(px[p], njx);   // == pi - pj exactly
            unsigned long long dy = add2(py[p], njy);
            unsigned long long dz = add2(pz[p], njz);
            unsigned long long t  = mul2(dz, dz);
            fma2(t, dy, dy);
            fma2(t, dx, dx);
            float2 d2p = unpack2(t);
#pragma unroll
            for (int h = 0; h < 2; h++) {
                int r = 2 * p + h;
                float d2 = h ? d2p.y : d2p.x;
                unsigned mask = __ballot_sync(FULL, d2 <= th[r]);  // conservative filter
                if (mask) {                                         // warp-uniform
                    unsigned long long key =
                        ((unsigned long long)__float_as_uint(d2) << 32) | (unsigned)j;
                    while (mask) {                                  // warp-uniform
                        int src = __ffs(mask) - 1;
                        mask &= mask - 1;
                        unsigned long long cand = __shfl_sync(FULL, key, src);
                        if (cand < tk[r]) {                         // warp-uniform (exact)
                            unsigned long long prev = __shfl_up_sync(FULL, cur[r], 1);
                            bool bigger = cur[r] > cand;
                            unsigned long long ins =
                                (lane > 0 && prev > cand) ? prev : cand;
                            cur[r] = bigger ? ins : cur[r];
                            tk[r] = __shfl_sync(FULL, cur[r], 15);
                            th[r] = __uint_as_float((unsigned)(tk[r] >> 32));
                        }
                    }
                }
            }
        }
    }

    if (lane < KNNK) {
#pragma unroll
        for (int r = 0; r < 8; r++)
            g_knn[((size_t)b * NPTS + i0 + r) * KNNK + lane] =
                (int)(unsigned)(cur[r] & 0xffffffffu);
    }
}

// ---------------- GEMM core (R4-exact): C = A[Mx128] @ B[128xN] (+bias) --------------
// 256 threads, tile 128M x 64N, 8M x 4N per thread (f32x2 pairs over M). Measured:
// 53.5us gemm_out, regs=76, occ=33%, fma=58%.
#define GBM 128
#define GBN 64
#define GBK 32
#define SAS 130   // padded (even) stride for transposed A tile

template <int N>
__device__ __forceinline__ void gemm_body(const float* __restrict__ A,
                                          const float* __restrict__ B,
                                          const float* __restrict__ bias,
                                          float* __restrict__ C,
                                          int m0, int n0) {
    __shared__ float sA[GBK * SAS];   // [k][m] transposed, ~16.6 KB
    __shared__ float sB[GBK * GBN];   // [k][n], 8 KB

    int tid = threadIdx.x;
    int tx  = tid & 15;        // n: 16 threads * 4 cols
    int ty  = tid >> 4;        // m: 16 threads * 8 rows

    unsigned long long acc[4][4];
#pragma unroll
    for (int i = 0; i < 4; i++)
#pragma unroll
        for (int j = 0; j < 4; j++) acc[i][j] = 0ull;   // bits of (0.f, 0.f)

    for (int k0 = 0; k0 < CCH; k0 += GBK) {
        // A tile: 128 rows x 32 cols, stored transposed
#pragma unroll
        for (int p = 0; p < 4; p++) {
            int f  = tid + 256 * p;            // 0..1023
            int m  = f >> 3;
            int kq = f & 7;
            float4 a4 = *reinterpret_cast<const float4*>(
                A + (size_t)(m0 + m) * CCH + k0 + kq * 4);
            float* d = sA + (kq * 4) * SAS + m;
            d[0 * SAS] = a4.x;
            d[1 * SAS] = a4.y;
            d[2 * SAS] = a4.z;
            d[3 * SAS] = a4.w;
        }
        // B tile: 32 rows x 64 cols
#pragma unroll
        for (int p = 0; p < 2; p++) {
            int f  = tid + 256 * p;            // 0..511
            int kr = f >> 4;
            int nq = f & 15;
            *reinterpret_cast<float4*>(sB + kr * GBN + nq * 4) =
                *reinterpret_cast<const float4*>(
                    B + (size_t)(k0 + kr) * N + n0 + nq * 4);
        }
        __syncthreads();

#pragma unroll
        for (int kk = 0; kk < GBK; kk++) {
            const float* ap = sA + kk * SAS + ty * 8;   // 8B-aligned (even offsets)
            unsigned long long a0 = *reinterpret_cast<const unsigned long long*>(ap + 0);
            unsigned long long a1 = *reinterpret_cast<const unsigned long long*>(ap + 2);
            unsigned long long a2 = *reinterpret_cast<const unsigned long long*>(ap + 4);
            unsigned long long a3 = *reinterpret_cast<const unsigned long long*>(ap + 6);
            float4 b4 = *reinterpret_cast<const float4*>(sB + kk * GBN + tx * 4);
            unsigned long long bd0 = dup2(b4.x);
            unsigned long long bd1 = dup2(b4.y);
            unsigned long long bd2 = dup2(b4.z);
            unsigned long long bd3 = dup2(b4.w);
            fma2(acc[0][0], a0, bd0); fma2(acc[0][1], a0, bd1);
            fma2(acc[0][2], a0, bd2); fma2(acc[0][3], a0, bd3);
            fma2(acc[1][0], a1, bd0); fma2(acc[1][1], a1, bd1);
            fma2(acc[1][2], a1, bd2); fma2(acc[1][3], a1, bd3);
            fma2(acc[2][0], a2, bd0); fma2(acc[2][1], a2, bd1);
            fma2(acc[2][2], a2, bd2); fma2(acc[2][3], a2, bd3);
            fma2(acc[3][0], a3, bd0); fma2(acc[3][1], a3, bd1);
            fma2(acc[3][2], a3, bd2); fma2(acc[3][3], a3, bd3);
        }
        __syncthreads();
    }

    float4 bv = make_float4(0.f, 0.f, 0.f, 0.f);
    if (bias) bv = *reinterpret_cast<const float4*>(bias + n0 + tx * 4);

#pragma unroll
    for (int i = 0; i < 4; i++) {
        float2 c0 = unpack2(acc[i][0]);
        float2 c1 = unpack2(acc[i][1]);
        float2 c2 = unpack2(acc[i][2]);
        float2 c3 = unpack2(acc[i][3]);
        int m = m0 + ty * 8 + 2 * i;
        float4 lo = make_float4(c0.x + bv.x, c1.x + bv.y, c2.x + bv.z, c3.x + bv.w);
        float4 hi = make_float4(c0.y + bv.x, c1.y + bv.y, c2.y + bv.z, c3.y + bv.w);
        *reinterpret_cast<float4*>(C + (size_t)m * N + n0 + tx * 4) = lo;
        *reinterpret_cast<float4*>(C + (size_t)(m + 1) * N + n0 + tx * 4) = hi;
    }
}

// input projections: z in {0,1,2} -> (Wsrc->g_asrc, Wdst->g_adst, Wval->g_val)
__global__ __launch_bounds__(256) void gemm_in_kernel(const float* __restrict__ x,
                                                      const float* __restrict__ Wsrc,
                                                      const float* __restrict__ Wdst,
                                                      const float* __restrict__ Wval) {
    const float* B;
    float* C;
    switch (blockIdx.z) {
        case 0:  B = Wsrc; C = g_asrc; break;
        case 1:  B = Wdst; C = g_adst; break;
        default: B = Wval; C = g_val;  break;
    }
    gemm_body<CCH>(x, B, nullptr, C, blockIdx.x * GBM, blockIdx.y * GBN);
}

// output projection: g_attn @ Wout + bout -> out
__global__ __launch_bounds__(256) void gemm_out_kernel(const float* __restrict__ Wout,
                                                       const float* __restrict__ bout,
                                                       float* __restrict__ out) {
    gemm_body<HOUT>(g_attn, Wout, bout, out, blockIdx.x * GBM, blockIdx.y * GBN);
}

// ---------------- attention: one row per 128-thread block, thread = channel ----------
__global__ __launch_bounds__(128) void attn_kernel(const float* __restrict__ pos,
                                                   const float* __restrict__ Wpos,
                                                   const float* __restrict__ bpos) {
    int row = blockIdx.x;          // b*NPTS + i
    int b   = row >> 12;
    int i   = row & (NPTS - 1);
    int c   = threadIdx.x;

    __shared__ float srel[KNNK][3];
    __shared__ int   sj[KNNK];

    if (c < KNNK) {
        int j = g_knn[(size_t)row * KNNK + c];
        sj[c] = j;
        const float* pb = pos + (size_t)b * NPTS * 3;
        srel[c][0] = pb[i * 3 + 0] - pb[j * 3 + 0];
        srel[c][1] = pb[i * 3 + 1] - pb[j * 3 + 1];
        srel[c][2] = pb[i * 3 + 2] - pb[j * 3 + 2];
    }
    __syncthreads();

    float w0 = Wpos[c];
    float w1 = Wpos[CCH + c];
    float w2 = Wpos[2 * CCH + c];
    float bp = bpos[c];
    float ad = g_adst[(size_t)row * CCH + c];

    float alpha[KNNK], vd[KNNK];
    float mx = -3.4e38f;
#pragma unroll
    for (int k = 0; k < KNNK; k++) {
        int j = sj[k];
        size_t base = ((size_t)b * NPTS + j) * CCH + c;
        float as = g_asrc[base];
        float vv = g_val[base];
        float dl = fmaf(srel[k][0], w0, fmaf(srel[k][1], w1, fmaf(srel[k][2], w2, bp)));
        alpha[k] = (ad - as) + dl;
        vd[k]    = vv + dl;
        mx = fmaxf(mx, alpha[k]);
    }
    float s = 0.f, accv = 0.f;
#pragma unroll
    for (int k = 0; k < KNNK; k++) {
        float e = __expf(alpha[k] - mx);
        s += e;
        accv = fmaf(e, vd[k], accv);
    }
    g_attn[(size_t)row * CCH + c] = accv / s;
}

// ---------------- launch (kernel launches ONLY — graph-capture safe) ----------------
extern "C" void kernel_launch(void* const* d_in, const int* in_sizes, int n_in,
                              void* d_out, int out_size) {
    const float* x    = (const float*)d_in[0];
    const float* pos  = (const float*)d_in[1];
    const float* Wsrc = (const float*)d_in[2];
    const float* Wdst = (const float*)d_in[3];
    const float* Wval = (const float*)d_in[4];
    const float* Wpos = (const float*)d_in[5];
    const float* bpos = (const float*)d_in[6];
    const float* Wout = (const float*)d_in[7];
    const float* bout = (const float*)d_in[8];
    float* out = (float*)d_out;

    knn_kernel<<<BATCH * (NPTS / 64), 256>>>(pos);

    dim3 g1(ROWS / GBM, CCH / GBN, 3);
    gemm_in_kernel<<<g1, 256>>>(x, Wsrc, Wdst, Wval);

    attn_kernel<<<ROWS, 128>>>(pos, Wpos, bpos);

    dim3 g2(ROWS / GBM, HOUT / GBN);
    gemm_out_kernel<<<g2, 256>>>(Wout, bout, out);
}

// round 10
// speedup vs baseline: 1.6413x; 1.2363x over previous
#include <cuda_runtime.h>
#include <cstdint>
#include <cstddef>

#define BATCH 8
#define NPTS  4096
#define CCH   128
#define HOUT  256
#define KNNK  16
#define ROWS  (BATCH * NPTS)

// ---------------- scratch (static __device__ — no runtime allocation) ----------------
__device__ float g_asrc[ROWS * CCH];
__device__ float g_adst[ROWS * CCH];
__device__ float g_val [ROWS * CCH];
__device__ float g_attn[ROWS * CCH];
__device__ int   g_knn [ROWS * KNNK];

// ---------------- packed f32x2 helpers ----------------
__device__ __forceinline__ unsigned long long dup2(float x) {
    unsigned long long r;
    asm("mov.b64 %0, {%1, %1};" : "=l"(r) : "f"(x));
    return r;
}
__device__ __forceinline__ void fma2(unsigned long long& d, unsigned long long a,
                                     unsigned long long b) {
    asm("fma.rn.f32x2 %0, %1, %2, %0;" : "+l"(d) : "l"(a), "l"(b));
}
__device__ __forceinline__ float2 unpack2(unsigned long long v) {
    float2 r;
    asm("mov.b64 {%0, %1}, %2;" : "=f"(r.x), "=f"(r.y) : "l"(v));
    return r;
}

// ---------------- KNN: warp per 4 rows, warp-collective top-16 ------------------------
// (R4 structure; insert path modified: tk/th updated ONCE PER TILE, not per insert.)
// Sorted top-16 keys (ascending) per row live in lanes 0..15, one u64 per lane:
//   key = (float_bits(d2) << 32) | j   (d2 >= 0: bit order == value order; ties by idx)
// Correctness note: the sorted-insert is a no-op when cand >= lane15's key, so both the
// ballot threshold (th) and the u64 gate (tk) may be STALE — they only filter candidates
// that provably cannot enter the top-16. Final sets are exact.
__global__ __launch_bounds__(256) void knn_kernel(const float* __restrict__ pos) {
    __shared__ float2 sxy[NPTS];   // 32 KB
    __shared__ float  szv[NPTS];   // 16 KB

    const int bpb = NPTS / 32;            // 32 rows per block
    int b  = blockIdx.x / bpb;
    int rb = blockIdx.x % bpb;
    const float* pb = pos + (size_t)b * NPTS * 3;

    for (int t = threadIdx.x; t < NPTS; t += 256) {
        const float* p = pb + t * 3;
        sxy[t] = make_float2(p[0], p[1]);
        szv[t] = p[2];
    }
    __syncthreads();

    int warp = threadIdx.x >> 5;
    int lane = threadIdx.x & 31;
    const unsigned FULL = 0xffffffffu;
    int i0 = rb * 32 + warp * 4;          // this warp's 4 rows

    float3 pi[4];
    unsigned long long cur[4], tk[4];
    float th[4];
#pragma unroll
    for (int r = 0; r < 4; r++) {
        float2 q = sxy[i0 + r];
        pi[r] = make_float3(q.x, q.y, szv[i0 + r]);
        cur[r] = ~0ull;
        tk[r]  = ~0ull;
        th[r]  = __int_as_float(0x7f800000);   // +inf
    }

    for (int j0 = 0; j0 < NPTS; j0 += 32) {
        int j = j0 + lane;
        float2 pj = sxy[j];
        float  zj = szv[j];
#pragma unroll
        for (int r = 0; r < 4; r++) {
            float dx = pi[r].x - pj.x;
            float dy = pi[r].y - pj.y;
            float dz = pi[r].z - zj;
            float d2 = fmaf(dx, dx, fmaf(dy, dy, dz * dz));

            unsigned mask = __ballot_sync(FULL, d2 <= th[r]);   // stale-threshold filter
            if (mask) {                                          // warp-uniform
                unsigned long long key =
                    ((unsigned long long)__float_as_uint(d2) << 32) | (unsigned)j;
                bool changed = false;
                while (mask) {                                   // warp-uniform
                    int src = __ffs(mask) - 1;
                    mask &= mask - 1;
                    unsigned long long cand = __shfl_sync(FULL, key, src);
                    if (cand < tk[r]) {        // stale gate (exact-superset filter)
                        unsigned long long prev = __shfl_up_sync(FULL, cur[r], 1);
                        bool bigger = cur[r] > cand;
                        unsigned long long ins =
                            (lane > 0 && prev > cand) ? prev : cand;
                        cur[r] = bigger ? ins : cur[r];          // no-op if cand >= lane15
                        changed = true;
                    }
                }
                if (changed) {                                   // warp-uniform
                    tk[r] = __shfl_sync(FULL, cur[r], 15);       // once per tile
                    th[r] = __uint_as_float((unsigned)(tk[r] >> 32));
                }
            }
        }
    }

    if (lane < KNNK) {
#pragma unroll
        for (int r = 0; r < 4; r++)
            g_knn[((size_t)b * NPTS + i0 + r) * KNNK + lane] =
                (int)(unsigned)(cur[r] & 0xffffffffu);
    }
}

// ---------------- GEMM core (R4-exact): C = A[Mx128] @ B[128xN] (+bias) --------------
// 256 threads, tile 128M x 64N, 8M x 4N per thread (f32x2 pairs over M). Measured:
// 53.5us gemm_out, regs=76, occ=33%, fma=58%.
#define GBM 128
#define GBN 64
#define GBK 32
#define SAS 130   // padded (even) stride for transposed A tile

template <int N>
__device__ __forceinline__ void gemm_body(const float* __restrict__ A,
                                          const float* __restrict__ B,
                                          const float* __restrict__ bias,
                                          float* __restrict__ C,
                                          int m0, int n0) {
    __shared__ float sA[GBK * SAS];   // [k][m] transposed, ~16.6 KB
    __shared__ float sB[GBK * GBN];   // [k][n], 8 KB

    int tid = threadIdx.x;
    int tx  = tid & 15;        // n: 16 threads * 4 cols
    int ty  = tid >> 4;        // m: 16 threads * 8 rows

    unsigned long long acc[4][4];
#pragma unroll
    for (int i = 0; i < 4; i++)
#pragma unroll
        for (int j = 0; j < 4; j++) acc[i][j] = 0ull;   // bits of (0.f, 0.f)

    for (int k0 = 0; k0 < CCH; k0 += GBK) {
        // A tile: 128 rows x 32 cols, stored transposed
#pragma unroll
        for (int p = 0; p < 4; p++) {
            int f  = tid + 256 * p;            // 0..1023
            int m  = f >> 3;
            int kq = f & 7;
            float4 a4 = *reinterpret_cast<const float4*>(
                A + (size_t)(m0 + m) * CCH + k0 + kq * 4);
            float* d = sA + (kq * 4) * SAS + m;
            d[0 * SAS] = a4.x;
            d[1 * SAS] = a4.y;
            d[2 * SAS] = a4.z;
            d[3 * SAS] = a4.w;
        }
        // B tile: 32 rows x 64 cols
#pragma unroll
        for (int p = 0; p < 2; p++) {
            int f  = tid + 256 * p;            // 0..511
            int kr = f >> 4;
            int nq = f & 15;
            *reinterpret_cast<float4*>(sB + kr * GBN + nq * 4) =
                *reinterpret_cast<const float4*>(
                    B + (size_t)(k0 + kr) * N + n0 + nq * 4);
        }
        __syncthreads();

#pragma unroll
        for (int kk = 0; kk < GBK; kk++) {
            const float* ap = sA + kk * SAS + ty * 8;   // 8B-aligned (even offsets)
            unsigned long long a0 = *reinterpret_cast<const unsigned long long*>(ap + 0);
            unsigned long long a1 = *reinterpret_cast<const unsigned long long*>(ap + 2);
            unsigned long long a2 = *reinterpret_cast<const unsigned long long*>(ap + 4);
            unsigned long long a3 = *reinterpret_cast<const unsigned long long*>(ap + 6);
            float4 b4 = *reinterpret_cast<const float4*>(sB + kk * GBN + tx * 4);
            unsigned long long bd0 = dup2(b4.x);
            unsigned long long bd1 = dup2(b4.y);
            unsigned long long bd2 = dup2(b4.z);
            unsigned long long bd3 = dup2(b4.w);
            fma2(acc[0][0], a0, bd0); fma2(acc[0][1], a0, bd1);
            fma2(acc[0][2], a0, bd2); fma2(acc[0][3], a0, bd3);
            fma2(acc[1][0], a1, bd0); fma2(acc[1][1], a1, bd1);
            fma2(acc[1][2], a1, bd2); fma2(acc[1][3], a1, bd3);
            fma2(acc[2][0], a2, bd0); fma2(acc[2][1], a2, bd1);
            fma2(acc[2][2], a2, bd2); fma2(acc[2][3], a2, bd3);
            fma2(acc[3][0], a3, bd0); fma2(acc[3][1], a3, bd1);
            fma2(acc[3][2], a3, bd2); fma2(acc[3][3], a3, bd3);
        }
        __syncthreads();
    }

    float4 bv = make_float4(0.f, 0.f, 0.f, 0.f);
    if (bias) bv = *reinterpret_cast<const float4*>(bias + n0 + tx * 4);

#pragma unroll
    for (int i = 0; i < 4; i++) {
        float2 c0 = unpack2(acc[i][0]);
        float2 c1 = unpack2(acc[i][1]);
        float2 c2 = unpack2(acc[i][2]);
        float2 c3 = unpack2(acc[i][3]);
        int m = m0 + ty * 8 + 2 * i;
        float4 lo = make_float4(c0.x + bv.x, c1.x + bv.y, c2.x + bv.z, c3.x + bv.w);
        float4 hi = make_float4(c0.y + bv.x, c1.y + bv.y, c2.y + bv.z, c3.y + bv.w);
        *reinterpret_cast<float4*>(C + (size_t)m * N + n0 + tx * 4) = lo;
        *reinterpret_cast<float4*>(C + (size_t)(m + 1) * N + n0 + tx * 4) = hi;
    }
}

// input projections: z in {0,1,2} -> (Wsrc->g_asrc, Wdst->g_adst, Wval->g_val)
__global__ __launch_bounds__(256) void gemm_in_kernel(const float* __restrict__ x,
                                                      const float* __restrict__ Wsrc,
                                                      const float* __restrict__ Wdst,
                                                      const float* __restrict__ Wval) {
    const float* B;
    float* C;
    switch (blockIdx.z) {
        case 0:  B = Wsrc; C = g_asrc; break;
        case 1:  B = Wdst; C = g_adst; break;
        default: B = Wval; C = g_val;  break;
    }
    gemm_body<CCH>(x, B, nullptr, C, blockIdx.x * GBM, blockIdx.y * GBN);
}

// output projection: g_attn @ Wout + bout -> out
__global__ __launch_bounds__(256) void gemm_out_kernel(const float* __restrict__ Wout,
                                                       const float* __restrict__ bout,
                                                       float* __restrict__ out) {
    gemm_body<HOUT>(g_attn, Wout, bout, out, blockIdx.x * GBM, blockIdx.y * GBN);
}

// ---------------- attention: one row per 128-thread block, thread = channel ----------
__global__ __launch_bounds__(128) void attn_kernel(const float* __restrict__ pos,
                                                   const float* __restrict__ Wpos,
                                                   const float* __restrict__ bpos) {
    int row = blockIdx.x;          // b*NPTS + i
    int b   = row >> 12;
    int i   = row & (NPTS - 1);
    int c   = threadIdx.x;

    __shared__ float srel[KNNK][3];
    __shared__ int   sj[KNNK];

    if (c < KNNK) {
        int j = g_knn[(size_t)row * KNNK + c];
        sj[c] = j;
        const float* pb = pos + (size_t)b * NPTS * 3;
        srel[c][0] = pb[i * 3 + 0] - pb[j * 3 + 0];
        srel[c][1] = pb[i * 3 + 1] - pb[j * 3 + 1];
        srel[c][2] = pb[i * 3 + 2] - pb[j * 3 + 2];
    }
    __syncthreads();

    float w0 = Wpos[c];
    float w1 = Wpos[CCH + c];
    float w2 = Wpos[2 * CCH + c];
    float bp = bpos[c];
    float ad = g_adst[(size_t)row * CCH + c];

    float alpha[KNNK], vd[KNNK];
    float mx = -3.4e38f;
#pragma unroll
    for (int k = 0; k < KNNK; k++) {
        int j = sj[k];
        size_t base = ((size_t)b * NPTS + j) * CCH + c;
        float as = g_asrc[base];
        float vv = g_val[base];
        float dl = fmaf(srel[k][0], w0, fmaf(srel[k][1], w1, fmaf(srel[k][2], w2, bp)));
        alpha[k] = (ad - as) + dl;
        vd[k]    = vv + dl;
        mx = fmaxf(mx, alpha[k]);
    }
    float s = 0.f, accv = 0.f;
#pragma unroll
    for (int k = 0; k < KNNK; k++) {
        float e = __expf(alpha[k] - mx);
        s += e;
        accv = fmaf(e, vd[k], accv);
    }
    g_attn[(size_t)row * CCH + c] = accv / s;
}

// ---------------- launch (kernel launches ONLY — graph-capture safe) ----------------
extern "C" void kernel_launch(void* const* d_in, const int* in_sizes, int n_in,
                              void* d_out, int out_size) {
    const float* x    = (const float*)d_in[0];
    const float* pos  = (const float*)d_in[1];
    const float* Wsrc = (const float*)d_in[2];
    const float* Wdst = (const float*)d_in[3];
    const float* Wval = (const float*)d_in[4];
    const float* Wpos = (const float*)d_in[5];
    const float* bpos = (const float*)d_in[6];
    const float* Wout = (const float*)d_in[7];
    const float* bout = (const float*)d_in[8];
    float* out = (float*)d_out;

    knn_kernel<<<BATCH * (NPTS / 32), 256>>>(pos);

    dim3 g1(ROWS / GBM, CCH / GBN, 3);
    gemm_in_kernel<<<g1, 256>>>(x, Wsrc, Wdst, Wval);

    attn_kernel<<<ROWS, 128>>>(pos, Wpos, bpos);

    dim3 g2(ROWS / GBM, HOUT / GBN);
    gemm_out_kernel<<<g2, 256>>>(Wout, bout, out);
}